// round 3
// baseline (speedup 1.0000x reference)
#include <cuda_runtime.h>

#define BATCH 8
#define SEQ 1024
#define HID 1024
#define D2 128
#define NHEADS 12
#define NC 24

typedef unsigned long long u64;

// ---------------- scratch (device globals; no allocation) ----------------
__device__ float g_h[BATCH * SEQ * D2];        // 4 MB
__device__ float g_qT[BATCH * 64 * SEQ];       // 2 MB, layout [b][d][s], pre-scaled by 1/8
__device__ float g_kT[BATCH * 64 * SEQ];       // 2 MB, layout [b][d][s]
__device__ float g_bias[BATCH * NC * SEQ];     // 0.75 MB, layout [b][c][s], already (h@W2+b2)/2

// ---------------- f32x2 helpers (Blackwell packed fp32) ----------------
__device__ __forceinline__ u64 pack2(float lo, float hi) {
    u64 r; asm("mov.b64 %0, {%1,%2};" : "=l"(r) : "f"(lo), "f"(hi)); return r;
}
__device__ __forceinline__ void fma2(u64& d, u64 a, u64 b) {
    asm("fma.rn.f32x2 %0, %1, %2, %0;" : "+l"(d) : "l"(a), "l"(b));
}

// ---------------- cp.async helpers ----------------
__device__ __forceinline__ void cpa16(void* s, const void* g) {
    unsigned sa = (unsigned)__cvta_generic_to_shared(s);
    asm volatile("cp.async.cg.shared.global [%0], [%1], 16;\n" :: "r"(sa), "l"(g));
}
__device__ __forceinline__ void cpa_commit() { asm volatile("cp.async.commit_group;\n" ::: "memory"); }
template<int N> __device__ __forceinline__ void cpa_wait() {
    asm volatile("cp.async.wait_group %0;\n" :: "n"(N) : "memory");
}

// ---------------- tf32 mma (fp32 bits fed directly; HW truncates mantissa) ----------------
__device__ __forceinline__ void mma_tf32(float* d, const unsigned* a, const unsigned* b) {
    asm volatile("mma.sync.aligned.m16n8k8.row.col.f32.tf32.tf32.f32 "
        "{%0,%1,%2,%3}, {%4,%5,%6,%7}, {%8,%9}, {%0,%1,%2,%3};"
        : "+f"(d[0]), "+f"(d[1]), "+f"(d[2]), "+f"(d[3])
        : "r"(a[0]), "r"(a[1]), "r"(a[2]), "r"(a[3]), "r"(b[0]), "r"(b[1]));
}

// ---------------- kernel 1: h = X @ W1 + b1  (8192x128, K=1024), tensor cores ----------------
// 256 threads (8 warps, 2m x 4n), M-tile 64, K staged x16, 3-deep cp.async pipeline.
__global__ __launch_bounds__(256) void gemm1_kernel(const float* __restrict__ X,
                                                    const float* __restrict__ W1,
                                                    const float* __restrict__ b1) {
    __shared__ float As[3][64][20];    // [m][k], padded row=20 (conflict-free frag gather)
    __shared__ float Bs[3][16][132];   // [k][n], padded row=132
    const int t = threadIdx.x;
    const int m0 = blockIdx.x * 64;
    const int warp = t >> 5, lane = t & 31;
    const int g = lane >> 2, tg = lane & 3;
    const int wm = (warp & 1) * 32;     // warp m offset within tile
    const int wn = (warp >> 1) * 32;    // warp n offset

    // cp.async coords (constant across stages)
    const int a_r = t >> 2,  a_c = (t & 3) * 4;    // A: 64x16 = 256 16B-chunks
    const int b_r = t >> 5,  b_c = (t & 31) * 4;   // B: 16x128 = 512 chunks, 2/thread

    auto load_stage = [&](int buf, int s) {
        const int k0 = s * 16;
        cpa16(&As[buf][a_r][a_c],     &X[(size_t)(m0 + a_r) * HID + k0 + a_c]);
        cpa16(&Bs[buf][b_r][b_c],     &W1[(size_t)(k0 + b_r) * D2 + b_c]);
        cpa16(&Bs[buf][b_r + 8][b_c], &W1[(size_t)(k0 + b_r + 8) * D2 + b_c]);
        cpa_commit();
    };

    float acc[2][4][4];   // [m16][n8][frag]
#pragma unroll
    for (int ni = 0; ni < 4; ni++) {
        float blo = b1[wn + ni * 8 + 2 * tg];
        float bhi = b1[wn + ni * 8 + 2 * tg + 1];
#pragma unroll
        for (int mi = 0; mi < 2; mi++) {
            acc[mi][ni][0] = blo; acc[mi][ni][1] = bhi;
            acc[mi][ni][2] = blo; acc[mi][ni][3] = bhi;
        }
    }

    const int NS = HID / 16;   // 64 stages
    load_stage(0, 0);
    load_stage(1, 1);

    for (int s = 0; s < NS; s++) {
        if (s + 2 < NS) { load_stage((s + 2) % 3, s + 2); cpa_wait<2>(); }
        else if (s + 1 < NS) cpa_wait<1>();
        else cpa_wait<0>();
        __syncthreads();

        const float (*A)[20]  = As[s % 3];
        const float (*B)[132] = Bs[s % 3];
#pragma unroll
        for (int kk = 0; kk < 16; kk += 8) {
            unsigned af[2][4];
#pragma unroll
            for (int mi = 0; mi < 2; mi++) {
                const int rb = wm + mi * 16;
                af[mi][0] = __float_as_uint(A[rb + g][kk + tg]);
                af[mi][1] = __float_as_uint(A[rb + g + 8][kk + tg]);
                af[mi][2] = __float_as_uint(A[rb + g][kk + tg + 4]);
                af[mi][3] = __float_as_uint(A[rb + g + 8][kk + tg + 4]);
            }
            unsigned bf[4][2];
#pragma unroll
            for (int ni = 0; ni < 4; ni++) {
                const int nn = wn + ni * 8 + g;
                bf[ni][0] = __float_as_uint(B[kk + tg][nn]);
                bf[ni][1] = __float_as_uint(B[kk + tg + 4][nn]);
            }
#pragma unroll
            for (int mi = 0; mi < 2; mi++)
#pragma unroll
                for (int ni = 0; ni < 4; ni++)
                    mma_tf32(acc[mi][ni], af[mi], bf[ni]);
        }
        __syncthreads();
    }

#pragma unroll
    for (int mi = 0; mi < 2; mi++)
#pragma unroll
        for (int ni = 0; ni < 4; ni++) {
            const int row = m0 + wm + mi * 16 + g;
            const int col = wn + ni * 8 + 2 * tg;
            *(float2*)&g_h[(size_t)row * D2 + col]       = make_float2(acc[mi][ni][0], acc[mi][ni][1]);
            *(float2*)&g_h[(size_t)(row + 8) * D2 + col] = make_float2(acc[mi][ni][2], acc[mi][ni][3]);
        }
}

// ---------------- kernel 2: RoPE(q,k) transposed + bias = (h@W2+b2)/2 ----------------
__global__ __launch_bounds__(256) void ropebias_kernel(const float* __restrict__ W2,
                                                       const float* __restrict__ b2) {
    __shared__ float hs[32][132];
    __shared__ float ws[D2 * NC];
    const int t = threadIdx.x;
    const int r0 = blockIdx.x * 32;        // global row (b*1024+s) base
    const int b = r0 >> 10;
    const int s0 = r0 & 1023;

#pragma unroll
    for (int u = 0; u < 4; u++) {
        int idx = t + 256 * u;
        int sr = idx >> 5, jq = (idx & 31) * 4;
        *(float4*)&hs[sr][jq] = *(const float4*)&g_h[(size_t)(r0 + sr) * D2 + jq];
    }
#pragma unroll
    for (int u = 0; u < 12; u++) ws[t + 256 * u] = W2[t + 256 * u];
    __syncthreads();

    const int sl = t & 31;
    const int s = s0 + sl;
    const int dbase = t >> 5;
#pragma unroll
    for (int it = 0; it < 8; it++) {
        int d = dbase + it * 8;            // 0..63
        int j = d >> 1;                    // rope pair index
        float inv = exp2f((float)(2 * j) * (-13.287712379549449f / 64.0f));
        float ang = (float)s * inv;
        float sn, cs;
        sincosf(ang, &sn, &cs);
        float qA = hs[sl][4 * j],     qB = hs[sl][4 * j + 2];
        float kA = hs[sl][4 * j + 1], kB = hs[sl][4 * j + 3];
        float qv, kv;
        if (d & 1) { qv = qB * cs + qA * sn; kv = kB * cs + kA * sn; }
        else       { qv = qA * cs - qB * sn; kv = kA * cs - kB * sn; }
        g_qT[(size_t)(b * 64 + d) * SEQ + s] = qv * 0.125f;   // fold 1/sqrt(64)
        g_kT[(size_t)(b * 64 + d) * SEQ + s] = kv;
    }

    for (int cc = t >> 5; cc < NC; cc += 8) {
        float dot = b2[cc];
#pragma unroll
        for (int j = 0; j < D2; j += 4) {
            float4 h4 = *(float4*)&hs[sl][j];
            dot += h4.x * ws[(j + 0) * NC + cc] + h4.y * ws[(j + 1) * NC + cc]
                 + h4.z * ws[(j + 2) * NC + cc] + h4.w * ws[(j + 3) * NC + cc];
        }
        g_bias[(size_t)(b * NC + cc) * SEQ + s] = dot * 0.5f;
    }
}

// ---------------- kernel 3: logits = att + bq[m] + bk[n] with mask/row0/col0/tril ----------------
__global__ __launch_bounds__(256) void logits_kernel(const float* __restrict__ am,
                                                     float* __restrict__ out) {
    __shared__ float qs[64][64];          // [d][m]; reused as att[m][n] after compute
    __shared__ float ks[64][64];          // [d][n]
    __shared__ float bq[NHEADS][64];
    __shared__ float bk[NHEADS][64];
    __shared__ float amm[64], amn[64];
    __shared__ int s_maskone;

    const int t = threadIdx.x;
    const int b = blockIdx.z, mt = blockIdx.y, nt = blockIdx.x;
    const int m0 = mt * 64, n0 = nt * 64;

#pragma unroll
    for (int u = 0; u < 4; u++) {
        int idx = t + 256 * u;
        int d = idx >> 4, mq = (idx & 15) * 4;
        *(float4*)&qs[d][mq] = *(const float4*)&g_qT[(size_t)(b * 64 + d) * SEQ + m0 + mq];
        *(float4*)&ks[d][mq] = *(const float4*)&g_kT[(size_t)(b * 64 + d) * SEQ + n0 + mq];
    }
    if (t < 192) {
        int h = t >> 4, mq = (t & 15) * 4;
        *(float4*)&bq[h][mq] = *(const float4*)&g_bias[(size_t)(b * NC + 2 * h) * SEQ + m0 + mq];
        *(float4*)&bk[h][mq] = *(const float4*)&g_bias[(size_t)(b * NC + 2 * h + 1) * SEQ + n0 + mq];
    } else if (t < 208) {
        int u = t - 192; *(float4*)&amm[u * 4] = *(const float4*)&am[b * SEQ + m0 + u * 4];
    } else if (t < 224) {
        int u = t - 208; *(float4*)&amn[u * 4] = *(const float4*)&am[b * SEQ + n0 + u * 4];
    }
    __syncthreads();
    if (t == 0) {
        int ok = 1;
        for (int i = 0; i < 64; i++) ok &= (amm[i] == 1.0f) & (amn[i] == 1.0f);
        s_maskone = ok;
    }

    // att tile: thread computes 4m x 4n, packed along n pairs
    const int tm = t >> 4, tn = t & 15;
    const int ml = tm * 4, nl = tn * 4;
    u64 acc[4][2];
    u64 z = pack2(0.0f, 0.0f);
#pragma unroll
    for (int i = 0; i < 4; i++) { acc[i][0] = z; acc[i][1] = z; }

#pragma unroll 8
    for (int d = 0; d < 64; d++) {
        float4 q4 = *(float4*)&qs[d][ml];
        ulonglong2 kp = *(const ulonglong2*)&ks[d][nl];
        u64 q0 = pack2(q4.x, q4.x), q1 = pack2(q4.y, q4.y);
        u64 q2 = pack2(q4.z, q4.z), q3 = pack2(q4.w, q4.w);
        fma2(acc[0][0], q0, kp.x); fma2(acc[0][1], q0, kp.y);
        fma2(acc[1][0], q1, kp.x); fma2(acc[1][1], q1, kp.y);
        fma2(acc[2][0], q2, kp.x); fma2(acc[2][1], q2, kp.y);
        fma2(acc[3][0], q3, kp.x); fma2(acc[3][1], q3, kp.y);
    }
    __syncthreads();                       // everyone done reading qs/ks
    float (*atts)[64] = qs;                // reuse q tile smem for att[m][n]
#pragma unroll
    for (int i = 0; i < 4; i++) {
        *(u64*)&atts[ml + i][nl]     = acc[i][0];
        *(u64*)&atts[ml + i][nl + 2] = acc[i][1];
    }
    __syncthreads();

    const int maskone = s_maskone;
    const bool mt0 = (m0 == 0), nt0 = (n0 == 0);
    const bool allT = (m0 > n0 + 63);
    const bool anyT = (m0 + 63 > n0);
    const float NEG = -10000.0f, BIG = 1e12f;

    for (int h = 0; h < NHEADS; h++) {
        size_t base = (((size_t)(b * NHEADS + h)) * SEQ + m0) * SEQ + n0;
#pragma unroll
        for (int i = 0; i < 4; i++) {
            int idx = t + 256 * i;
            int m = idx >> 4, n = (idx & 15) * 4;
            float4 a4 = *(float4*)&atts[m][n];
            float bb = bq[h][m];
            float4 c4 = *(float4*)&bk[h][n];
            float4 v;
            v.x = a4.x + bb + c4.x; v.y = a4.y + bb + c4.y;
            v.z = a4.z + bb + c4.z; v.w = a4.w + bb + c4.w;
            if (!maskone) {
                float amv = amm[m];
                v.x -= (1.0f - amv * amn[n + 0]) * BIG;
                v.y -= (1.0f - amv * amn[n + 1]) * BIG;
                v.z -= (1.0f - amv * amn[n + 2]) * BIG;
                v.w -= (1.0f - amv * amn[n + 3]) * BIG;
            }
            if (mt0 && m == 0) { v.x = NEG; v.y = NEG; v.z = NEG; v.w = NEG; }
            if (nt0 && n == 0) v.x = NEG;
            if (allT) { v.x -= BIG; v.y -= BIG; v.z -= BIG; v.w -= BIG; }
            else if (anyT) {
                int gm = m0 + m, gn = n0 + n;
                if (gm > gn)     v.x -= BIG;
                if (gm > gn + 1) v.y -= BIG;
                if (gm > gn + 2) v.z -= BIG;
                if (gm > gn + 3) v.w -= BIG;
            }
            __stcs((float4*)(out + base + (size_t)m * SEQ + n), v);
        }
    }
}

// ---------------- launch ----------------
extern "C" void kernel_launch(void* const* d_in, const int* in_sizes, int n_in,
                              void* d_out, int out_size) {
    const float* X  = (const float*)d_in[0];
    const float* am = (const float*)d_in[1];
    const float* W1 = (const float*)d_in[2];
    const float* b1 = (const float*)d_in[3];
    const float* W2 = (const float*)d_in[4];
    const float* b2 = (const float*)d_in[5];
    float* out = (float*)d_out;

    gemm1_kernel<<<(BATCH * SEQ) / 64, 256>>>(X, W1, b1);
    ropebias_kernel<<<(BATCH * SEQ) / 32, 256>>>(W2, b2);
    dim3 g3(SEQ / 64, SEQ / 64, BATCH);
    logits_kernel<<<g3, 256>>>(am, out);
}

// round 4
// speedup vs baseline: 1.6770x; 1.6770x over previous
#include <cuda_runtime.h>

#define BATCH 8
#define SEQ 1024
#define HID 1024
#define D2 128
#define NHEADS 12
#define NC 24

typedef unsigned long long u64;

// ---------------- scratch (device globals; no allocation) ----------------
__device__ float g_qT[BATCH * 64 * SEQ];       // 2 MB, layout [b][d][s], pre-scaled by 1/8
__device__ float g_kT[BATCH * 64 * SEQ];       // 2 MB, layout [b][d][s]
__device__ float g_bias[BATCH * NC * SEQ];     // 0.75 MB, layout [b][c][s], already (h@W2+b2)/2

// ---------------- f32x2 helpers ----------------
__device__ __forceinline__ u64 pack2(float lo, float hi) {
    u64 r; asm("mov.b64 %0, {%1,%2};" : "=l"(r) : "f"(lo), "f"(hi)); return r;
}
__device__ __forceinline__ void fma2(u64& d, u64 a, u64 b) {
    asm("fma.rn.f32x2 %0, %1, %2, %0;" : "+l"(d) : "l"(a), "l"(b));
}

// ---------------- cp.async helpers ----------------
__device__ __forceinline__ void cpa16(void* s, const void* g) {
    unsigned sa = (unsigned)__cvta_generic_to_shared(s);
    asm volatile("cp.async.cg.shared.global [%0], [%1], 16;\n" :: "r"(sa), "l"(g));
}
__device__ __forceinline__ void cpa_commit() { asm volatile("cp.async.commit_group;\n" ::: "memory"); }
template<int N> __device__ __forceinline__ void cpa_wait() {
    asm volatile("cp.async.wait_group %0;\n" :: "n"(N) : "memory");
}

// ---------------- tf32 mma ----------------
__device__ __forceinline__ void mma_tf32(float* d, const unsigned* a, const unsigned* b) {
    asm volatile("mma.sync.aligned.m16n8k8.row.col.f32.tf32.tf32.f32 "
        "{%0,%1,%2,%3}, {%4,%5,%6,%7}, {%8,%9}, {%0,%1,%2,%3};"
        : "+f"(d[0]), "+f"(d[1]), "+f"(d[2]), "+f"(d[3])
        : "r"(a[0]), "r"(a[1]), "r"(a[2]), "r"(a[3]), "r"(b[0]), "r"(b[1]));
}

// smem geometry (floats)
#define AROW 36
#define BROW 136
#define A_ST (64 * AROW)            // 2304
#define B_ST (32 * BROW)            // 4352
#define NBUF 4
#define SMEM_FLOATS (NBUF * (A_ST + B_ST))   // 26624 floats = 106496 B
#define HROW 132

// ---------------- kernel 1: fused h=X@W1+b1 -> RoPE(q,k)T + bias ----------------
// 256 threads (8 warps, 2m x 4n), M-tile 64, K staged x32, 4-deep cp.async pipeline.
__global__ __launch_bounds__(256) void gemm_rope_kernel(const float* __restrict__ X,
                                                        const float* __restrict__ W1,
                                                        const float* __restrict__ b1,
                                                        const float* __restrict__ W2,
                                                        const float* __restrict__ b2) {
    extern __shared__ float smem[];
    float* Abase = smem;                    // NBUF x [64][AROW]
    float* Bbase = smem + NBUF * A_ST;      // NBUF x [32][BROW]

    const int t = threadIdx.x;
    const int m0 = blockIdx.x * 64;         // global row base (b*1024 + s0)
    const int warp = t >> 5, lane = t & 31;
    const int g = lane >> 2, tg = lane & 3;
    const int wm = (warp & 1) * 32;
    const int wn = (warp >> 1) * 32;

    // cp.async coords
    const int a_r0 = t >> 3,        a_c = (t & 7) * 4;   // +256 -> second half
    const int b_c = (t & 31) * 4;

    auto load_stage = [&](int buf, int s) {
        const int k0 = s * 32;
        float* A = Abase + buf * A_ST;
        float* B = Bbase + buf * B_ST;
        cpa16(&A[a_r0 * AROW + a_c],        &X[(size_t)(m0 + a_r0) * HID + k0 + a_c]);
        cpa16(&A[(a_r0 + 32) * AROW + a_c], &X[(size_t)(m0 + a_r0 + 32) * HID + k0 + a_c]);
#pragma unroll
        for (int u = 0; u < 4; u++) {
            int br = (t + 256 * u) >> 5;
            cpa16(&B[br * BROW + b_c], &W1[(size_t)(k0 + br) * D2 + b_c]);
        }
        cpa_commit();
    };

    float acc[2][4][4];
#pragma unroll
    for (int ni = 0; ni < 4; ni++) {
        float blo = b1[wn + ni * 8 + 2 * tg];
        float bhi = b1[wn + ni * 8 + 2 * tg + 1];
#pragma unroll
        for (int mi = 0; mi < 2; mi++) {
            acc[mi][ni][0] = blo; acc[mi][ni][1] = bhi;
            acc[mi][ni][2] = blo; acc[mi][ni][3] = bhi;
        }
    }

    const int NS = HID / 32;   // 32 stages
    load_stage(0, 0);
    load_stage(1, 1);
    load_stage(2, 2);

    for (int s = 0; s < NS; s++) {
        if (s + 3 < NS) { load_stage((s + 3) & 3, s + 3); cpa_wait<3>(); }
        else if (s + 2 < NS) cpa_wait<2>();
        else if (s + 1 < NS) cpa_wait<1>();
        else cpa_wait<0>();
        __syncthreads();

        const float* A = Abase + (s & 3) * A_ST;
        const float* B = Bbase + (s & 3) * B_ST;
#pragma unroll
        for (int kk = 0; kk < 32; kk += 8) {
            unsigned af[2][4];
#pragma unroll
            for (int mi = 0; mi < 2; mi++) {
                const int rb = wm + mi * 16;
                af[mi][0] = __float_as_uint(A[(rb + g) * AROW + kk + tg]);
                af[mi][1] = __float_as_uint(A[(rb + g + 8) * AROW + kk + tg]);
                af[mi][2] = __float_as_uint(A[(rb + g) * AROW + kk + tg + 4]);
                af[mi][3] = __float_as_uint(A[(rb + g + 8) * AROW + kk + tg + 4]);
            }
            unsigned bf[4][2];
#pragma unroll
            for (int ni = 0; ni < 4; ni++) {
                const int nn = wn + ni * 8 + g;
                bf[ni][0] = __float_as_uint(B[(kk + tg) * BROW + nn]);
                bf[ni][1] = __float_as_uint(B[(kk + tg + 4) * BROW + nn]);
            }
#pragma unroll
            for (int mi = 0; mi < 2; mi++)
#pragma unroll
                for (int ni = 0; ni < 4; ni++)
                    mma_tf32(acc[mi][ni], af[mi], bf[ni]);
        }
        __syncthreads();
    }

    // -------- epilogue: stash h tile in smem (reuse stage buffers) --------
    float* hs = smem;                 // [64][HROW]
    float* ws = smem + 64 * HROW;     // [128*24] W2
    __syncthreads();                  // all smem reads of mainloop done

#pragma unroll
    for (int mi = 0; mi < 2; mi++)
#pragma unroll
        for (int ni = 0; ni < 4; ni++) {
            const int row = wm + mi * 16 + g;
            const int col = wn + ni * 8 + 2 * tg;
            *(float2*)&hs[row * HROW + col]       = make_float2(acc[mi][ni][0], acc[mi][ni][1]);
            *(float2*)&hs[(row + 8) * HROW + col] = make_float2(acc[mi][ni][2], acc[mi][ni][3]);
        }
#pragma unroll
    for (int u = 0; u < 12; u++) ws[t + 256 * u] = W2[t + 256 * u];
    __syncthreads();

    const int b = m0 >> 10;
    const int s0 = m0 & 1023;
    const int sl = t & 63;            // row within tile
    const int dg = t >> 6;            // 0..3
    const int s = s0 + sl;
    const float* hrow = &hs[sl * HROW];

#pragma unroll
    for (int it = 0; it < 16; it++) {
        int d = dg + it * 4;          // 0..63
        int j = d >> 1;
        float inv = exp2f((float)(2 * j) * (-13.287712379549449f / 64.0f));
        float ang = (float)s * inv;
        float sn, cs;
        sincosf(ang, &sn, &cs);
        float qA = hrow[4 * j],     qB = hrow[4 * j + 2];
        float kA = hrow[4 * j + 1], kB = hrow[4 * j + 3];
        float qv, kv;
        if (d & 1) { qv = qB * cs + qA * sn; kv = kB * cs + kA * sn; }
        else       { qv = qA * cs - qB * sn; kv = kA * cs - kB * sn; }
        g_qT[(size_t)(b * 64 + d) * SEQ + s] = qv * 0.125f;   // fold 1/sqrt(64)
        g_kT[(size_t)(b * 64 + d) * SEQ + s] = kv;
    }

    for (int cc = dg; cc < NC; cc += 4) {
        float dot = b2[cc];
#pragma unroll
        for (int j = 0; j < D2; j += 4) {
            float4 h4 = *(const float4*)&hrow[j];
            dot += h4.x * ws[(j + 0) * NC + cc] + h4.y * ws[(j + 1) * NC + cc]
                 + h4.z * ws[(j + 2) * NC + cc] + h4.w * ws[(j + 3) * NC + cc];
        }
        g_bias[(size_t)(b * NC + cc) * SEQ + s] = dot * 0.5f;
    }
}

// ---------------- kernel 2: logits = att + bq[m] + bk[n] with mask/row0/col0/tril ----------------
__global__ __launch_bounds__(256) void logits_kernel(const float* __restrict__ am,
                                                     float* __restrict__ out) {
    __shared__ float qs[64][64];          // [d][m]; reused as att[m][n] after compute
    __shared__ float ks[64][64];          // [d][n]
    __shared__ float bq[NHEADS][64];
    __shared__ float bk[NHEADS][64];
    __shared__ float amm[64], amn[64];
    __shared__ int s_maskone;

    const int t = threadIdx.x;
    const int b = blockIdx.z, mt = blockIdx.y, nt = blockIdx.x;
    const int m0 = mt * 64, n0 = nt * 64;

#pragma unroll
    for (int u = 0; u < 4; u++) {
        int idx = t + 256 * u;
        int d = idx >> 4, mq = (idx & 15) * 4;
        *(float4*)&qs[d][mq] = *(const float4*)&g_qT[(size_t)(b * 64 + d) * SEQ + m0 + mq];
        *(float4*)&ks[d][mq] = *(const float4*)&g_kT[(size_t)(b * 64 + d) * SEQ + n0 + mq];
    }
    if (t < 192) {
        int h = t >> 4, mq = (t & 15) * 4;
        *(float4*)&bq[h][mq] = *(const float4*)&g_bias[(size_t)(b * NC + 2 * h) * SEQ + m0 + mq];
        *(float4*)&bk[h][mq] = *(const float4*)&g_bias[(size_t)(b * NC + 2 * h + 1) * SEQ + n0 + mq];
    } else if (t < 208) {
        int u = t - 192; *(float4*)&amm[u * 4] = *(const float4*)&am[b * SEQ + m0 + u * 4];
    } else if (t < 224) {
        int u = t - 208; *(float4*)&amn[u * 4] = *(const float4*)&am[b * SEQ + n0 + u * 4];
    }
    __syncthreads();
    if (t == 0) {
        int ok = 1;
        for (int i = 0; i < 64; i++) ok &= (amm[i] == 1.0f) & (amn[i] == 1.0f);
        s_maskone = ok;
    }

    // att tile: thread computes 4m x 4n
    const int tm = t >> 4, tn = t & 15;
    const int ml = tm * 4, nl = tn * 4;
    u64 acc[4][2];
    u64 z = pack2(0.0f, 0.0f);
#pragma unroll
    for (int i = 0; i < 4; i++) { acc[i][0] = z; acc[i][1] = z; }

#pragma unroll 8
    for (int d = 0; d < 64; d++) {
        float4 q4 = *(float4*)&qs[d][ml];
        ulonglong2 kp = *(const ulonglong2*)&ks[d][nl];
        u64 q0 = pack2(q4.x, q4.x), q1 = pack2(q4.y, q4.y);
        u64 q2 = pack2(q4.z, q4.z), q3 = pack2(q4.w, q4.w);
        fma2(acc[0][0], q0, kp.x); fma2(acc[0][1], q0, kp.y);
        fma2(acc[1][0], q1, kp.x); fma2(acc[1][1], q1, kp.y);
        fma2(acc[2][0], q2, kp.x); fma2(acc[2][1], q2, kp.y);
        fma2(acc[3][0], q3, kp.x); fma2(acc[3][1], q3, kp.y);
    }
    __syncthreads();
    float (*atts)[64] = qs;                // reuse q tile smem for att[m][n]
#pragma unroll
    for (int i = 0; i < 4; i++) {
        *(u64*)&atts[ml + i][nl]     = acc[i][0];
        *(u64*)&atts[ml + i][nl + 2] = acc[i][1];
    }
    __syncthreads();

    const int maskone = s_maskone;
    const bool mt0 = (m0 == 0), nt0 = (n0 == 0);
    const bool allT = (m0 > n0 + 63);
    const bool anyT = (m0 + 63 > n0);
    const float NEG = -10000.0f, BIG = 1e12f;

    for (int h = 0; h < NHEADS; h++) {
        size_t base = (((size_t)(b * NHEADS + h)) * SEQ + m0) * SEQ + n0;
#pragma unroll
        for (int i = 0; i < 4; i++) {
            int idx = t + 256 * i;
            int m = idx >> 4, n = (idx & 15) * 4;
            float4 a4 = *(float4*)&atts[m][n];
            float bb = bq[h][m];
            float4 c4 = *(float4*)&bk[h][n];
            float4 v;
            v.x = a4.x + bb + c4.x; v.y = a4.y + bb + c4.y;
            v.z = a4.z + bb + c4.z; v.w = a4.w + bb + c4.w;
            if (!maskone) {
                float amv = amm[m];
                v.x -= (1.0f - amv * amn[n + 0]) * BIG;
                v.y -= (1.0f - amv * amn[n + 1]) * BIG;
                v.z -= (1.0f - amv * amn[n + 2]) * BIG;
                v.w -= (1.0f - amv * amn[n + 3]) * BIG;
            }
            if (mt0 && m == 0) { v.x = NEG; v.y = NEG; v.z = NEG; v.w = NEG; }
            if (nt0 && n == 0) v.x = NEG;
            if (allT) { v.x -= BIG; v.y -= BIG; v.z -= BIG; v.w -= BIG; }
            else if (anyT) {
                int gm = m0 + m, gn = n0 + n;
                if (gm > gn)     v.x -= BIG;
                if (gm > gn + 1) v.y -= BIG;
                if (gm > gn + 2) v.z -= BIG;
                if (gm > gn + 3) v.w -= BIG;
            }
            __stcs((float4*)(out + base + (size_t)m * SEQ + n), v);
        }
    }
}

// ---------------- launch ----------------
extern "C" void kernel_launch(void* const* d_in, const int* in_sizes, int n_in,
                              void* d_out, int out_size) {
    const float* X  = (const float*)d_in[0];
    const float* am = (const float*)d_in[1];
    const float* W1 = (const float*)d_in[2];
    const float* b1 = (const float*)d_in[3];
    const float* W2 = (const float*)d_in[4];
    const float* b2 = (const float*)d_in[5];
    float* out = (float*)d_out;

    cudaFuncSetAttribute(gemm_rope_kernel,
                         cudaFuncAttributeMaxDynamicSharedMemorySize,
                         SMEM_FLOATS * 4);
    gemm_rope_kernel<<<(BATCH * SEQ) / 64, 256, SMEM_FLOATS * 4>>>(X, W1, b1, W2, b2);
    dim3 g3(SEQ / 64, SEQ / 64, BATCH);
    logits_kernel<<<g3, 256>>>(am, out);
}

// round 5
// speedup vs baseline: 1.7784x; 1.0605x over previous
#include <cuda_runtime.h>

#define BATCH 8
#define SEQ 1024
#define HID 1024
#define D2 128
#define NHEADS 12
#define NC 24

typedef unsigned long long u64;

// ---------------- scratch (device globals; no allocation) ----------------
__device__ float g_qT[BATCH * 64 * SEQ];       // [b][d][s], pre-scaled by 1/8
__device__ float g_kT[BATCH * 64 * SEQ];       // [b][d][s]
__device__ float g_bias[BATCH * NC * SEQ];     // [b][c][s], already (h@W2+b2)/2
__device__ float2 g_trig[32][1024];            // [j][s] = (sin, cos)

// ---------------- f32x2 helpers ----------------
__device__ __forceinline__ u64 pack2(float lo, float hi) {
    u64 r; asm("mov.b64 %0, {%1,%2};" : "=l"(r) : "f"(lo), "f"(hi)); return r;
}
__device__ __forceinline__ void unpack2(u64 v, float& lo, float& hi) {
    asm("mov.b64 {%0,%1}, %2;" : "=f"(lo), "=f"(hi) : "l"(v));
}
__device__ __forceinline__ void fma2(u64& d, u64 a, u64 b) {
    asm("fma.rn.f32x2 %0, %1, %2, %0;" : "+l"(d) : "l"(a), "l"(b));
}

// ---------------- cp.async helpers ----------------
__device__ __forceinline__ void cpa16(void* s, const void* g) {
    unsigned sa = (unsigned)__cvta_generic_to_shared(s);
    asm volatile("cp.async.cg.shared.global [%0], [%1], 16;\n" :: "r"(sa), "l"(g));
}
__device__ __forceinline__ void cpa_commit() { asm volatile("cp.async.commit_group;\n" ::: "memory"); }
template<int N> __device__ __forceinline__ void cpa_wait() {
    asm volatile("cp.async.wait_group %0;\n" :: "n"(N) : "memory");
}

// ---------------- tf32 mma ----------------
__device__ __forceinline__ void mma_tf32(float* d, const unsigned* a, const unsigned* b) {
    asm volatile("mma.sync.aligned.m16n8k8.row.col.f32.tf32.tf32.f32 "
        "{%0,%1,%2,%3}, {%4,%5,%6,%7}, {%8,%9}, {%0,%1,%2,%3};"
        : "+f"(d[0]), "+f"(d[1]), "+f"(d[2]), "+f"(d[3])
        : "r"(a[0]), "r"(a[1]), "r"(a[2]), "r"(a[3]), "r"(b[0]), "r"(b[1]));
}

// smem geometry (floats)
#define AROW 36
#define BROW 136
#define A_ST (64 * AROW)
#define B_ST (32 * BROW)
#define NBUF 4
#define SMEM_FLOATS (NBUF * (A_ST + B_ST))   // 26624 floats = 106496 B
#define HROW 132

// ---------------- kernel 0: trig table ----------------
__global__ __launch_bounds__(256) void trig_kernel() {
    int idx = blockIdx.x * 256 + threadIdx.x;   // 0..32767
    int j = idx >> 10, s = idx & 1023;
    float inv = exp2f((float)(2 * j) * (-13.287712379549449f / 64.0f));
    float ang = (float)s * inv;
    float sn, cs;
    sincosf(ang, &sn, &cs);
    g_trig[j][s] = make_float2(sn, cs);
}

// ---------------- kernel 1: fused h=X@W1+b1 -> RoPE(q,k)T + bias ----------------
__global__ __launch_bounds__(256) void gemm_rope_kernel(const float* __restrict__ X,
                                                        const float* __restrict__ W1,
                                                        const float* __restrict__ b1,
                                                        const float* __restrict__ W2,
                                                        const float* __restrict__ b2) {
    extern __shared__ float smem[];
    float* Abase = smem;                    // NBUF x [64][AROW]
    float* Bbase = smem + NBUF * A_ST;      // NBUF x [32][BROW]

    const int t = threadIdx.x;
    const int m0 = blockIdx.x * 64;
    const int warp = t >> 5, lane = t & 31;
    const int g = lane >> 2, tg = lane & 3;
    const int wm = (warp & 1) * 32;
    const int wn = (warp >> 1) * 32;

    const int a_r0 = t >> 3, a_c = (t & 7) * 4;
    const int b_c = (t & 31) * 4;

    auto load_stage = [&](int buf, int s) {
        const int k0 = s * 32;
        float* A = Abase + buf * A_ST;
        float* B = Bbase + buf * B_ST;
        cpa16(&A[a_r0 * AROW + a_c],        &X[(size_t)(m0 + a_r0) * HID + k0 + a_c]);
        cpa16(&A[(a_r0 + 32) * AROW + a_c], &X[(size_t)(m0 + a_r0 + 32) * HID + k0 + a_c]);
#pragma unroll
        for (int u = 0; u < 4; u++) {
            int br = (t + 256 * u) >> 5;
            cpa16(&B[br * BROW + b_c], &W1[(size_t)(k0 + br) * D2 + b_c]);
        }
        cpa_commit();
    };

    float acc[2][4][4];
#pragma unroll
    for (int ni = 0; ni < 4; ni++) {
        float blo = b1[wn + ni * 8 + 2 * tg];
        float bhi = b1[wn + ni * 8 + 2 * tg + 1];
#pragma unroll
        for (int mi = 0; mi < 2; mi++) {
            acc[mi][ni][0] = blo; acc[mi][ni][1] = bhi;
            acc[mi][ni][2] = blo; acc[mi][ni][3] = bhi;
        }
    }

    const int NS = HID / 32;
    load_stage(0, 0);
    load_stage(1, 1);
    load_stage(2, 2);

    for (int s = 0; s < NS; s++) {
        if (s + 3 < NS) { load_stage((s + 3) & 3, s + 3); cpa_wait<3>(); }
        else if (s + 2 < NS) cpa_wait<2>();
        else if (s + 1 < NS) cpa_wait<1>();
        else cpa_wait<0>();
        __syncthreads();

        const float* A = Abase + (s & 3) * A_ST;
        const float* B = Bbase + (s & 3) * B_ST;
#pragma unroll
        for (int kk = 0; kk < 32; kk += 8) {
            unsigned af[2][4];
#pragma unroll
            for (int mi = 0; mi < 2; mi++) {
                const int rb = wm + mi * 16;
                af[mi][0] = __float_as_uint(A[(rb + g) * AROW + kk + tg]);
                af[mi][1] = __float_as_uint(A[(rb + g + 8) * AROW + kk + tg]);
                af[mi][2] = __float_as_uint(A[(rb + g) * AROW + kk + tg + 4]);
                af[mi][3] = __float_as_uint(A[(rb + g + 8) * AROW + kk + tg + 4]);
            }
            unsigned bf[4][2];
#pragma unroll
            for (int ni = 0; ni < 4; ni++) {
                const int nn = wn + ni * 8 + g;
                bf[ni][0] = __float_as_uint(B[(kk + tg) * BROW + nn]);
                bf[ni][1] = __float_as_uint(B[(kk + tg + 4) * BROW + nn]);
            }
#pragma unroll
            for (int mi = 0; mi < 2; mi++)
#pragma unroll
                for (int ni = 0; ni < 4; ni++)
                    mma_tf32(acc[mi][ni], af[mi], bf[ni]);
        }
        __syncthreads();
    }

    // -------- epilogue: stash h tile in smem (reuse stage buffers) --------
    float* hs = smem;                 // [64][HROW]
    float* ws = smem + 64 * HROW;     // [128*24] W2
    __syncthreads();

#pragma unroll
    for (int mi = 0; mi < 2; mi++)
#pragma unroll
        for (int ni = 0; ni < 4; ni++) {
            const int row = wm + mi * 16 + g;
            const int col = wn + ni * 8 + 2 * tg;
            *(float2*)&hs[row * HROW + col]       = make_float2(acc[mi][ni][0], acc[mi][ni][1]);
            *(float2*)&hs[(row + 8) * HROW + col] = make_float2(acc[mi][ni][2], acc[mi][ni][3]);
        }
#pragma unroll
    for (int u = 0; u < 12; u++) ws[t + 256 * u] = W2[t + 256 * u];
    __syncthreads();

    const int b = m0 >> 10;
    const int s0 = m0 & 1023;
    const int sl = t & 63;
    const int dg = t >> 6;            // 0..3
    const int s = s0 + sl;
    const float* hrow = &hs[sl * HROW];

#pragma unroll
    for (int it = 0; it < 16; it++) {
        int d = dg + it * 4;          // 0..63
        int j = d >> 1;
        float2 tc = g_trig[j][s];
        float sn = tc.x, cs = tc.y;
        float qA = hrow[4 * j],     qB = hrow[4 * j + 2];
        float kA = hrow[4 * j + 1], kB = hrow[4 * j + 3];
        float qv, kv;
        if (d & 1) { qv = qB * cs + qA * sn; kv = kB * cs + kA * sn; }
        else       { qv = qA * cs - qB * sn; kv = kA * cs - kB * sn; }
        g_qT[(size_t)(b * 64 + d) * SEQ + s] = qv * 0.125f;
        g_kT[(size_t)(b * 64 + d) * SEQ + s] = kv;
    }

    for (int cc = dg; cc < NC; cc += 4) {
        float dot = b2[cc];
#pragma unroll
        for (int j = 0; j < D2; j += 4) {
            float4 h4 = *(const float4*)&hrow[j];
            dot += h4.x * ws[(j + 0) * NC + cc] + h4.y * ws[(j + 1) * NC + cc]
                 + h4.z * ws[(j + 2) * NC + cc] + h4.w * ws[(j + 3) * NC + cc];
        }
        g_bias[(size_t)(b * NC + cc) * SEQ + s] = dot * 0.5f;
    }
}

// ---------------- kernel 2: logits ----------------
// -1e12 in fp32 = -999999995904; adding |x|<32768 rounds back to it exactly.
#define CBIG -999999995904.0f

__global__ __launch_bounds__(256) void logits_kernel(const float* __restrict__ am,
                                                     float* __restrict__ out) {
    __shared__ float qs[64][64];
    __shared__ float ks[64][64];
    __shared__ float bq[NHEADS][64];
    __shared__ float bk[NHEADS][64];
    __shared__ float amm[64], amn[64];
    __shared__ int s_maskone;

    const int t = threadIdx.x;
    const int b = blockIdx.z, mt = blockIdx.y, nt = blockIdx.x;
    const int m0 = mt * 64, n0 = nt * 64;
    const int tm = t >> 4, tn = t & 15;
    const int ml = tm * 4, nl = tn * 4;

    if (t == 0) s_maskone = 1;
    if (t < 16)      *(float4*)&amm[t * 4]        = *(const float4*)&am[b * SEQ + m0 + t * 4];
    else if (t < 32) *(float4*)&amn[(t - 16) * 4] = *(const float4*)&am[b * SEQ + n0 + (t - 16) * 4];
    __syncthreads();
    if (t < 64 && (amm[t] != 1.0f || amn[t] != 1.0f)) s_maskone = 0;
    __syncthreads();
    const int maskone = s_maskone;

    // ---------- fast path: fully-masked tile -> constant ----------
    if (maskone && m0 > n0 + 63) {
        const float4 C4 = make_float4(CBIG, CBIG, CBIG, CBIG);
        for (int h = 0; h < NHEADS; h++) {
            size_t base = (((size_t)(b * NHEADS + h)) * SEQ + m0) * SEQ + n0;
#pragma unroll
            for (int i = 0; i < 4; i++) {
                int idx = t + 256 * i;
                int m = idx >> 4, n = (idx & 15) * 4;
                __stcs((float4*)(out + base + (size_t)m * SEQ + n), C4);
            }
        }
        return;
    }

    // ---------- slow path ----------
#pragma unroll
    for (int u = 0; u < 4; u++) {
        int idx = t + 256 * u;
        int d = idx >> 4, mq = (idx & 15) * 4;
        *(float4*)&qs[d][mq] = *(const float4*)&g_qT[(size_t)(b * 64 + d) * SEQ + m0 + mq];
        *(float4*)&ks[d][mq] = *(const float4*)&g_kT[(size_t)(b * 64 + d) * SEQ + n0 + mq];
    }
    if (t < 192) {
        int h = t >> 4, mq = (t & 15) * 4;
        *(float4*)&bq[h][mq] = *(const float4*)&g_bias[(size_t)(b * NC + 2 * h) * SEQ + m0 + mq];
        *(float4*)&bk[h][mq] = *(const float4*)&g_bias[(size_t)(b * NC + 2 * h + 1) * SEQ + n0 + mq];
    }
    __syncthreads();

    u64 acc[4][2];
    u64 z = pack2(0.0f, 0.0f);
#pragma unroll
    for (int i = 0; i < 4; i++) { acc[i][0] = z; acc[i][1] = z; }

#pragma unroll 8
    for (int d = 0; d < 64; d++) {
        float4 q4 = *(float4*)&qs[d][ml];
        ulonglong2 kp = *(const ulonglong2*)&ks[d][nl];
        u64 q0 = pack2(q4.x, q4.x), q1 = pack2(q4.y, q4.y);
        u64 q2 = pack2(q4.z, q4.z), q3 = pack2(q4.w, q4.w);
        fma2(acc[0][0], q0, kp.x); fma2(acc[0][1], q0, kp.y);
        fma2(acc[1][0], q1, kp.x); fma2(acc[1][1], q1, kp.y);
        fma2(acc[2][0], q2, kp.x); fma2(acc[2][1], q2, kp.y);
        fma2(acc[3][0], q3, kp.x); fma2(acc[3][1], q3, kp.y);
    }

    float att[4][4];
#pragma unroll
    for (int i = 0; i < 4; i++) {
        unpack2(acc[i][0], att[i][0], att[i][1]);
        unpack2(acc[i][1], att[i][2], att[i][3]);
    }

    const float BIG = 1e12f;
    // fold mask + tril into att (head-independent)
#pragma unroll
    for (int i = 0; i < 4; i++) {
        int gm = m0 + ml + i;
#pragma unroll
        for (int j = 0; j < 4; j++) {
            int gn = n0 + nl + j;
            if (!maskone) att[i][j] -= (1.0f - amm[ml + i] * amn[nl + j]) * BIG;
            if (gm > gn) att[i][j] -= BIG;
        }
    }

    const bool rowzero = (m0 == 0 && tm == 0);   // only i==0 is global row 0
    const bool colzero = (n0 == 0 && tn == 0);   // only j==0 is global col 0
    const float NEG = -10000.0f;

    for (int h = 0; h < NHEADS; h++) {
        size_t base = (((size_t)(b * NHEADS + h)) * SEQ + m0) * SEQ + n0;
        float4 bkv = *(float4*)&bk[h][nl];
#pragma unroll
        for (int i = 0; i < 4; i++) {
            float bb = bq[h][ml + i];
            float4 v;
            v.x = att[i][0] + bb + bkv.x;
            v.y = att[i][1] + bb + bkv.y;
            v.z = att[i][2] + bb + bkv.z;
            v.w = att[i][3] + bb + bkv.w;
            if (rowzero && i == 0) { v.x = NEG; v.y = NEG; v.z = NEG; v.w = NEG; }
            if (colzero) v.x = (m0 + ml + i == 0) ? NEG : CBIG;
            __stcs((float4*)(out + base + (size_t)(ml + i) * SEQ + nl), v);
        }
    }
}

// ---------------- launch ----------------
extern "C" void kernel_launch(void* const* d_in, const int* in_sizes, int n_in,
                              void* d_out, int out_size) {
    const float* X  = (const float*)d_in[0];
    const float* am = (const float*)d_in[1];
    const float* W1 = (const float*)d_in[2];
    const float* b1 = (const float*)d_in[3];
    const float* W2 = (const float*)d_in[4];
    const float* b2 = (const float*)d_in[5];
    float* out = (float*)d_out;

    cudaFuncSetAttribute(gemm_rope_kernel,
                         cudaFuncAttributeMaxDynamicSharedMemorySize,
                         SMEM_FLOATS * 4);
    trig_kernel<<<128, 256>>>();
    gemm_rope_kernel<<<(BATCH * SEQ) / 64, 256, SMEM_FLOATS * 4>>>(X, W1, b1, W2, b2);
    dim3 g3(SEQ / 64, SEQ / 64, BATCH);
    logits_kernel<<<g3, 256>>>(am, out);
}